// round 13
// baseline (speedup 1.0000x reference)
#include <cuda_runtime.h>
#include <cuda_fp16.h>
#include <cstdint>
#include <cstddef>

#define BATCH 8192
#define DIN   4096
#define DOUT  4096

// fp16 scratch (module-load allocation; legal per harness rules)
__device__ __half g_Xh[(size_t)BATCH * DIN];   // 64 MB
__device__ __half g_Wh[(size_t)DOUT  * DIN];   // 32 MB

// ---------------------------------------------------------------------------
// Fused conversion kernel: x fp32->fp16 and w*mask fp32->fp16 in one launch.
// ---------------------------------------------------------------------------
static constexpr int NX4 = (BATCH * DIN) / 4;   // 8388608
static constexpr int NW4 = (DOUT  * DIN) / 4;   // 4194304

__device__ __forceinline__ uint2 cvt4(float4 v) {
    __half2 h0 = __floats2half2_rn(v.x, v.y);
    __half2 h1 = __floats2half2_rn(v.z, v.w);
    uint2 u;
    u.x = *reinterpret_cast<uint32_t*>(&h0);
    u.y = *reinterpret_cast<uint32_t*>(&h1);
    return u;
}

__global__ void __launch_bounds__(256)
convert_both_kernel(const float4* __restrict__ x,
                    const float4* __restrict__ w,
                    const float4* __restrict__ m) {
    int i0 = (blockIdx.x * blockDim.x + threadIdx.x) * 2;
    if (i0 + 1 < NX4) {
        float4 v0 = __ldg(x + i0);
        float4 v1 = __ldg(x + i0 + 1);
        reinterpret_cast<uint2*>(g_Xh)[i0]     = cvt4(v0);
        reinterpret_cast<uint2*>(g_Xh)[i0 + 1] = cvt4(v1);
    } else if (i0 < NX4 + NW4) {
        int j0 = i0 - NX4;
        if (i0 >= NX4 && j0 + 1 < NW4) {
            float4 w0 = __ldg(w + j0), m0v = __ldg(m + j0);
            float4 w1 = __ldg(w + j0 + 1), m1v = __ldg(m + j0 + 1);
            float4 a0 = make_float4(w0.x * m0v.x, w0.y * m0v.y, w0.z * m0v.z, w0.w * m0v.w);
            float4 a1 = make_float4(w1.x * m1v.x, w1.y * m1v.y, w1.z * m1v.z, w1.w * m1v.w);
            reinterpret_cast<uint2*>(g_Wh)[j0]     = cvt4(a0);
            reinterpret_cast<uint2*>(g_Wh)[j0 + 1] = cvt4(a1);
        }
    }
}

// ---------------------------------------------------------------------------
// GEMM: out[8192,4096] = Xh @ Wh^T, fp16 in / fp32 accum via mma.sync.m16n8k16
// CTA tile 128x128x32-per-stage, 8 warps (4M x 2N), warp tile 32x64.
// 6 stages, compile-time slot phases (period 3). Load addressing fully
// hoisted: per-thread global row pointers + swizzled smem offsets computed
// once; load_stage is 4 cp.asyncs with constant-folded addresses.
// ---------------------------------------------------------------------------
static constexpr int STAGES  = 6;
static constexpr int STAGE_B = 16384;              // A 8KB + B 8KB
static constexpr int SMEM_B  = STAGES * STAGE_B;   // 96 KB

// 64B rows (32 halfs). 16B chunk c in 0..3, swizzle chunk XOR (row>>1)&3.
__device__ __forceinline__ uint32_t sw_off(int row, int c16) {
    return (uint32_t)(row * 64 + (((c16 ^ ((row >> 1) & 3)) << 4)));
}

__device__ __forceinline__ uint32_t smem_u32(const void* p) {
    uint32_t a;
    asm("{ .reg .u64 t; cvta.to.shared.u64 t, %1; cvt.u32.u64 %0, t; }"
        : "=r"(a) : "l"(p));
    return a;
}

__device__ __forceinline__ void ldsm_x4(uint32_t* r, uint32_t addr) {
    asm volatile("ldmatrix.sync.aligned.m8n8.x4.shared.b16 {%0,%1,%2,%3}, [%4];"
                 : "=r"(r[0]), "=r"(r[1]), "=r"(r[2]), "=r"(r[3]) : "r"(addr));
}

__device__ __forceinline__ void mma16816(float* c, const uint32_t* a,
                                         uint32_t b0, uint32_t b1) {
    asm volatile(
        "mma.sync.aligned.m16n8k16.row.col.f32.f16.f16.f32 "
        "{%0,%1,%2,%3}, {%4,%5,%6,%7}, {%8,%9}, {%0,%1,%2,%3};"
        : "+f"(c[0]), "+f"(c[1]), "+f"(c[2]), "+f"(c[3])
        : "r"(a[0]), "r"(a[1]), "r"(a[2]), "r"(a[3]), "r"(b0), "r"(b1));
}

__device__ __forceinline__ void stg_cs_v2(float* p, float a, float b) {
    float2 v = make_float2(a, b);
    asm volatile("st.global.cs.v2.f32 [%0], {%1, %2};"
                 :: "l"(p), "f"(v.x), "f"(v.y) : "memory");
}

__device__ __forceinline__ void cp16(uint32_t so, const __half* gp) {
    asm volatile("cp.async.cg.shared.global [%0], [%1], 16;"
                 :: "r"(so), "l"(gp) : "memory");
}

// Hoisted load context: this thread's two A rows are (tid>>2) and (tid>>2)+64,
// same for B; +64 rows = +64*DIN halfs in gmem and +4096 bytes in smem
// (swizzle XOR invariant under row+64).
struct LoadCtx {
    const __half* gpA;   // g_Xh + (m0 + (tid>>2))*DIN + (tid&3)*8
    const __half* gpB;   // g_Wh + (n0 + (tid>>2))*DIN + (tid&3)*8
    uint32_t soA;        // st_base + sw_off(tid>>2, tid&3)
    uint32_t soB;        // st_base + 8192 + sw_off(tid>>2, tid&3)
};

template <int SLOT>
__device__ __forceinline__ void load_stage(const LoadCtx& L, int k0) {
    constexpr uint32_t SB = (uint32_t)(SLOT * STAGE_B);
    constexpr int R64 = 64 * DIN;
    const __half* pa = L.gpA + k0;
    const __half* pb = L.gpB + k0;
    cp16(L.soA + SB,         pa);
    cp16(L.soA + SB + 4096u, pa + R64);
    cp16(L.soB + SB,         pb);
    cp16(L.soB + SB + 4096u, pb + R64);
    asm volatile("cp.async.commit_group;" ::: "memory");
}

// Fragment set for one k16 chunk: A halves + first two B quads.
struct FragPre {
    uint32_t A0[4], A1[4], B0[4], B1[4];
};

__device__ __forceinline__ void ld_pre(FragPre& f, uint32_t sb, uint32_t x,
                                       uint32_t offA0, uint32_t offA1,
                                       const uint32_t* offB) {
    ldsm_x4(f.A0, (sb + offA0) ^ x);
    ldsm_x4(f.A1, (sb + offA1) ^ x);
    ldsm_x4(f.B0, (sb + offB[0]) ^ x);
    ldsm_x4(f.B1, (sb + offB[1]) ^ x);
}

// Process one k16 chunk (16 HMMAs). Loads its own B2/B3 and the next chunk's
// pre-fragments (possibly in another stage / next phase), interleaved.
__device__ __forceinline__ void chunk(float acc[2][8][4], FragPre& cur, FragPre& nxt,
                                      uint32_t sb, uint32_t x,
                                      uint32_t nsb, uint32_t nx,
                                      uint32_t offA0, uint32_t offA1,
                                      const uint32_t* offB) {
    uint32_t B2[4], B3[4];
    ldsm_x4(B2, (sb + offB[2]) ^ x);
    mma16816(acc[0][0], cur.A0, cur.B0[0], cur.B0[2]);
    mma16816(acc[0][1], cur.A0, cur.B0[1], cur.B0[3]);
    ldsm_x4(B3, (sb + offB[3]) ^ x);
    mma16816(acc[1][0], cur.A1, cur.B0[0], cur.B0[2]);
    mma16816(acc[1][1], cur.A1, cur.B0[1], cur.B0[3]);
    ldsm_x4(nxt.A0, (nsb + offA0) ^ nx);
    mma16816(acc[0][2], cur.A0, cur.B1[0], cur.B1[2]);
    mma16816(acc[0][3], cur.A0, cur.B1[1], cur.B1[3]);
    ldsm_x4(nxt.A1, (nsb + offA1) ^ nx);
    mma16816(acc[1][2], cur.A1, cur.B1[0], cur.B1[2]);
    mma16816(acc[1][3], cur.A1, cur.B1[1], cur.B1[3]);
    ldsm_x4(nxt.B0, (nsb + offB[0]) ^ nx);
    mma16816(acc[0][4], cur.A0, B2[0], B2[2]);
    mma16816(acc[0][5], cur.A0, B2[1], B2[3]);
    ldsm_x4(nxt.B1, (nsb + offB[1]) ^ nx);
    mma16816(acc[1][4], cur.A1, B2[0], B2[2]);
    mma16816(acc[1][5], cur.A1, B2[1], B2[3]);
    mma16816(acc[0][6], cur.A0, B3[0], B3[2]);
    mma16816(acc[0][7], cur.A0, B3[1], B3[3]);
    mma16816(acc[1][6], cur.A1, B3[0], B3[2]);
    mma16816(acc[1][7], cur.A1, B3[1], B3[3]);
}

// One phase = 2 k-steps (4 k16 chunks), slot indices compile-time.
// LAST skips the trailing wait+sync (nothing consumed after).
template <int P, bool LAST = false>
__device__ __forceinline__ void phase(float acc[2][8][4], FragPre& f0, FragPre& f1,
                                      uint32_t st_base, int kf, const LoadCtx& L,
                                      uint32_t offA0, uint32_t offA1,
                                      const uint32_t* offB) {
    constexpr int S1 = (P + 1) % STAGES;
    constexpr int S2 = (P + 2) % STAGES;
    constexpr int F0 = (P + 4) % STAGES;
    constexpr int F1 = (P + 5) % STAGES;
    const uint32_t sb0 = st_base + (uint32_t)(P  * STAGE_B);
    const uint32_t sb1 = st_base + (uint32_t)(S1 * STAGE_B);
    const uint32_t sb2 = st_base + (uint32_t)(S2 * STAGE_B);

    if (kf < 128) load_stage<F0>(L, kf * 32);

    chunk(acc, f0, f1, sb0, 0u,  sb0, 32u, offA0, offA1, offB);
    chunk(acc, f1, f0, sb0, 32u, sb1, 0u,  offA0, offA1, offB);

    if (kf + 1 < 128) load_stage<F1>(L, (kf + 1) * 32);

    chunk(acc, f0, f1, sb1, 0u,  sb1, 32u, offA0, offA1, offB);
    chunk(acc, f1, f0, sb1, 32u, sb2, 0u,  offA0, offA1, offB);

    if (!LAST) {
        asm volatile("cp.async.wait_group 1;" ::: "memory");
        __syncthreads();
    }
}

__global__ void __launch_bounds__(256, 2)
expander_gemm_kernel(float* __restrict__ out) {
    extern __shared__ char smem_raw[];
    const uint32_t st_base = smem_u32(smem_raw);

    const int tid  = threadIdx.x;
    const int lane = tid & 31;
    const int warp = tid >> 5;
    const int wm = warp & 3;        // 4 warps along M
    const int wn = warp >> 2;       // 2 warps along N
    const int mbase = wm * 32;
    const int nbase = wn * 64;

    // Rasterization: groups of 8 M-tiles x all 32 N-tiles for L2 reuse.
    const int TILES_N = DOUT / 128;               // 32
    const int per_g = 8 * TILES_N;                // 256
    int g   = blockIdx.x / per_g;
    int rem = blockIdx.x % per_g;
    int mt = g * 8 + (rem & 7);
    int nt = rem >> 3;
    const int m0 = mt * 128, n0 = nt * 128;

    // Hoisted load addressing.
    LoadCtx L;
    {
        int row = tid >> 2, c = tid & 3;
        L.gpA = g_Xh + (size_t)(m0 + row) * DIN + c * 8;
        L.gpB = g_Wh + (size_t)(n0 + row) * DIN + c * 8;
        L.soA = st_base + sw_off(row, c);
        L.soB = st_base + 8192u + sw_off(row, c);
    }

    // Per-thread ldmatrix addressing (kk=1 addr = kk0 ^ 32 in swizzle domain).
    const int a_row  = lane & 15;
    const int a_cadd = lane >> 4;
    const int b_row  = (lane & 7) + ((lane >> 3) & 1) * 8;
    const int b_cadd = lane >> 4;

    int rA0 = mbase + a_row, rA1 = mbase + 16 + a_row;
    const uint32_t offA0 = (uint32_t)rA0 * 64 + ((uint32_t)(a_cadd ^ ((rA0 >> 1) & 3)) << 4);
    const uint32_t offA1 = (uint32_t)rA1 * 64 + ((uint32_t)(a_cadd ^ ((rA1 >> 1) & 3)) << 4);
    uint32_t offB[4];
#pragma unroll
    for (int i4 = 0; i4 < 4; i4++) {
        int r = nbase + i4 * 16 + b_row;
        offB[i4] = 8192u + (uint32_t)r * 64 + ((uint32_t)(b_cadd ^ ((r >> 1) & 3)) << 4);
    }

    float acc[2][8][4];
#pragma unroll
    for (int a = 0; a < 2; a++)
#pragma unroll
        for (int b = 0; b < 8; b++)
#pragma unroll
            for (int c = 0; c < 4; c++) acc[a][b][c] = 0.f;

    // Prologue: fill stages 0..3 (k-steps 0..3).
    load_stage<0>(L, 0 * 32);
    load_stage<1>(L, 1 * 32);
    load_stage<2>(L, 2 * 32);
    load_stage<3>(L, 3 * 32);

    asm volatile("cp.async.wait_group 1;" ::: "memory");
    __syncthreads();
    FragPre f0, f1;
    ld_pre(f0, st_base, 0u, offA0, offA1, offB);

    // 64 phases = 21 unrolled triples (slot period 3) + 1 tail phase.
    int kf = 4;
#pragma unroll 1
    for (int trip = 0; trip < 21; trip++) {
        phase<0>(acc, f0, f1, st_base, kf,     L, offA0, offA1, offB);
        phase<2>(acc, f0, f1, st_base, kf + 2, L, offA0, offA1, offB);
        phase<4>(acc, f0, f1, st_base, kf + 4, L, offA0, offA1, offB);
        kf += 6;
    }
    phase<0, true>(acc, f0, f1, st_base, kf, L, offA0, offA1, offB);  // kf=130

    // Epilogue: streaming stores (output is never re-read; keep it out of L2).
    const int gid = lane >> 2, tig = lane & 3;
#pragma unroll
    for (int im = 0; im < 2; im++) {
        int r0 = m0 + mbase + im * 16 + gid;
#pragma unroll
        for (int j8 = 0; j8 < 8; j8++) {
            int col = n0 + nbase + j8 * 8 + tig * 2;
            stg_cs_v2(out + (size_t)r0 * DOUT + col,
                      acc[im][j8][0], acc[im][j8][1]);
            stg_cs_v2(out + (size_t)(r0 + 8) * DOUT + col,
                      acc[im][j8][2], acc[im][j8][3]);
        }
    }
}

// ---------------------------------------------------------------------------
// Launch
// ---------------------------------------------------------------------------
extern "C" void kernel_launch(void* const* d_in, const int* in_sizes, int n_in,
                              void* d_out, int out_size) {
    const float* x    = (const float*)d_in[0];
    const float* w    = (const float*)d_in[1];
    const float* mask = (const float*)d_in[2];
    float* out = (float*)d_out;

    {
        int ntot2 = (NX4 + NW4) / 2;   // 2 float4 per thread
        convert_both_kernel<<<(ntot2 + 255) / 256, 256>>>(
            (const float4*)x, (const float4*)w, (const float4*)mask);
    }

    static bool attr_set = false;
    if (!attr_set) {
        cudaFuncSetAttribute(expander_gemm_kernel,
                             cudaFuncAttributeMaxDynamicSharedMemorySize, SMEM_B);
        attr_set = true;
    }
    int grid = (BATCH / 128) * (DOUT / 128);   // 2048
    expander_gemm_kernel<<<grid, 256, SMEM_B>>>(out);
}

// round 14
// speedup vs baseline: 1.0373x; 1.0373x over previous
#include <cuda_runtime.h>
#include <cuda_fp16.h>
#include <cstdint>
#include <cstddef>

#define BATCH 8192
#define DIN   4096
#define DOUT  4096

// fp16 scratch (module-load allocation; legal per harness rules)
__device__ __half g_Xh[(size_t)BATCH * DIN];   // 64 MB
__device__ __half g_Wh[(size_t)DOUT  * DIN];   // 32 MB

// ---------------------------------------------------------------------------
// Fused conversion kernel: x fp32->fp16 and w*mask fp32->fp16 in one launch.
// ---------------------------------------------------------------------------
static constexpr int NX4 = (BATCH * DIN) / 4;   // 8388608
static constexpr int NW4 = (DOUT  * DIN) / 4;   // 4194304

__device__ __forceinline__ uint2 cvt4(float4 v) {
    __half2 h0 = __floats2half2_rn(v.x, v.y);
    __half2 h1 = __floats2half2_rn(v.z, v.w);
    uint2 u;
    u.x = *reinterpret_cast<uint32_t*>(&h0);
    u.y = *reinterpret_cast<uint32_t*>(&h1);
    return u;
}

__global__ void __launch_bounds__(256)
convert_both_kernel(const float4* __restrict__ x,
                    const float4* __restrict__ w,
                    const float4* __restrict__ m) {
    int i0 = (blockIdx.x * blockDim.x + threadIdx.x) * 2;
    if (i0 + 1 < NX4) {
        float4 v0 = __ldg(x + i0);
        float4 v1 = __ldg(x + i0 + 1);
        reinterpret_cast<uint2*>(g_Xh)[i0]     = cvt4(v0);
        reinterpret_cast<uint2*>(g_Xh)[i0 + 1] = cvt4(v1);
    } else if (i0 < NX4 + NW4) {
        int j0 = i0 - NX4;
        if (i0 >= NX4 && j0 + 1 < NW4) {
            float4 w0 = __ldg(w + j0), m0v = __ldg(m + j0);
            float4 w1 = __ldg(w + j0 + 1), m1v = __ldg(m + j0 + 1);
            float4 a0 = make_float4(w0.x * m0v.x, w0.y * m0v.y, w0.z * m0v.z, w0.w * m0v.w);
            float4 a1 = make_float4(w1.x * m1v.x, w1.y * m1v.y, w1.z * m1v.z, w1.w * m1v.w);
            reinterpret_cast<uint2*>(g_Wh)[j0]     = cvt4(a0);
            reinterpret_cast<uint2*>(g_Wh)[j0 + 1] = cvt4(a1);
        }
    }
}

// ---------------------------------------------------------------------------
// GEMM: out[8192,4096] = Xh @ Wh^T, fp16 in / fp32 accum via mma.sync.m16n8k16
// CTA tile 128x128x32-per-stage, 8 warps (4M x 2N), warp tile 32x64.
// 6 stages, compile-time slot phases (period 3). LDSM addresses written as
// sb + (off ^ x): XOR is loop-invariant (hoistable), sb folds to immediate.
// ---------------------------------------------------------------------------
static constexpr int STAGES  = 6;
static constexpr int STAGE_B = 16384;              // A 8KB + B 8KB
static constexpr int SMEM_B  = STAGES * STAGE_B;   // 96 KB

// 64B rows (32 halfs). 16B chunk c in 0..3, swizzle chunk XOR (row>>1)&3.
__device__ __forceinline__ uint32_t sw_off(int row, int c16) {
    return (uint32_t)(row * 64 + (((c16 ^ ((row >> 1) & 3)) << 4)));
}

__device__ __forceinline__ uint32_t smem_u32(const void* p) {
    uint32_t a;
    asm("{ .reg .u64 t; cvta.to.shared.u64 t, %1; cvt.u32.u64 %0, t; }"
        : "=r"(a) : "l"(p));
    return a;
}

__device__ __forceinline__ void ldsm_x4(uint32_t* r, uint32_t addr) {
    asm volatile("ldmatrix.sync.aligned.m8n8.x4.shared.b16 {%0,%1,%2,%3}, [%4];"
                 : "=r"(r[0]), "=r"(r[1]), "=r"(r[2]), "=r"(r[3]) : "r"(addr));
}

__device__ __forceinline__ void mma16816(float* c, const uint32_t* a,
                                         uint32_t b0, uint32_t b1) {
    asm volatile(
        "mma.sync.aligned.m16n8k16.row.col.f32.f16.f16.f32 "
        "{%0,%1,%2,%3}, {%4,%5,%6,%7}, {%8,%9}, {%0,%1,%2,%3};"
        : "+f"(c[0]), "+f"(c[1]), "+f"(c[2]), "+f"(c[3])
        : "r"(a[0]), "r"(a[1]), "r"(a[2]), "r"(a[3]), "r"(b0), "r"(b1));
}

__device__ __forceinline__ void stg_cs_v2(float* p, float a, float b) {
    float2 v = make_float2(a, b);
    asm volatile("st.global.cs.v2.f32 [%0], {%1, %2};"
                 :: "l"(p), "f"(v.x), "f"(v.y) : "memory");
}

__device__ __forceinline__ void load_stage(uint32_t st_base, int slot,
                                           int k0, int m0, int n0, int tid) {
    uint32_t base = st_base + (uint32_t)slot * STAGE_B;
#pragma unroll
    for (int i = 0; i < 4; i++) {
        int cid = i * 256 + tid;            // 0..1023 (A: <512, B: >=512)
        const __half* gp;
        uint32_t so;
        if (cid < 512) {                    // A: 128 rows x 4 chunks
            int row = cid >> 2, c = cid & 3;
            gp = g_Xh + (size_t)(m0 + row) * DIN + k0 + c * 8;
            so = base + sw_off(row, c);
        } else {                            // B: 128 rows x 4 chunks
            int row = (cid - 512) >> 2, c = cid & 3;
            gp = g_Wh + (size_t)(n0 + row) * DIN + k0 + c * 8;
            so = base + 8192 + sw_off(row, c);
        }
        asm volatile("cp.async.cg.shared.global [%0], [%1], 16;"
                     :: "r"(so), "l"(gp) : "memory");
    }
    asm volatile("cp.async.commit_group;" ::: "memory");
}

// Fragment set for one k16 chunk: A halves + first two B quads.
struct FragPre {
    uint32_t A0[4], A1[4], B0[4], B1[4];
};

// NOTE: addresses use sb + (off ^ x). Valid because sb is a multiple of 16384
// and off < 16384 (no carry into bit 5), so (sb+off)^x == sb+(off^x). The XOR
// is loop-invariant -> hoisted once; sb (compile-time per phase) folds into
// the LDSM immediate.
__device__ __forceinline__ void ld_pre(FragPre& f, uint32_t sb, uint32_t x,
                                       uint32_t offA0, uint32_t offA1,
                                       const uint32_t* offB) {
    ldsm_x4(f.A0, sb + (offA0 ^ x));
    ldsm_x4(f.A1, sb + (offA1 ^ x));
    ldsm_x4(f.B0, sb + (offB[0] ^ x));
    ldsm_x4(f.B1, sb + (offB[1] ^ x));
}

// Process one k16 chunk (16 HMMAs). Loads its own B2/B3 and the next chunk's
// pre-fragments (possibly in another stage / next phase), interleaved.
__device__ __forceinline__ void chunk(float acc[2][8][4], FragPre& cur, FragPre& nxt,
                                      uint32_t sb, uint32_t x,
                                      uint32_t nsb, uint32_t nx,
                                      uint32_t offA0, uint32_t offA1,
                                      const uint32_t* offB) {
    uint32_t B2[4], B3[4];
    ldsm_x4(B2, sb + (offB[2] ^ x));
    mma16816(acc[0][0], cur.A0, cur.B0[0], cur.B0[2]);
    mma16816(acc[0][1], cur.A0, cur.B0[1], cur.B0[3]);
    ldsm_x4(B3, sb + (offB[3] ^ x));
    mma16816(acc[1][0], cur.A1, cur.B0[0], cur.B0[2]);
    mma16816(acc[1][1], cur.A1, cur.B0[1], cur.B0[3]);
    ldsm_x4(nxt.A0, nsb + (offA0 ^ nx));
    mma16816(acc[0][2], cur.A0, cur.B1[0], cur.B1[2]);
    mma16816(acc[0][3], cur.A0, cur.B1[1], cur.B1[3]);
    ldsm_x4(nxt.A1, nsb + (offA1 ^ nx));
    mma16816(acc[1][2], cur.A1, cur.B1[0], cur.B1[2]);
    mma16816(acc[1][3], cur.A1, cur.B1[1], cur.B1[3]);
    ldsm_x4(nxt.B0, nsb + (offB[0] ^ nx));
    mma16816(acc[0][4], cur.A0, B2[0], B2[2]);
    mma16816(acc[0][5], cur.A0, B2[1], B2[3]);
    ldsm_x4(nxt.B1, nsb + (offB[1] ^ nx));
    mma16816(acc[1][4], cur.A1, B2[0], B2[2]);
    mma16816(acc[1][5], cur.A1, B2[1], B2[3]);
    mma16816(acc[0][6], cur.A0, B3[0], B3[2]);
    mma16816(acc[0][7], cur.A0, B3[1], B3[3]);
    mma16816(acc[1][6], cur.A1, B3[0], B3[2]);
    mma16816(acc[1][7], cur.A1, B3[1], B3[3]);
}

// One phase = 2 k-steps (4 k16 chunks), slot indices compile-time.
template <int P, bool LAST = false>
__device__ __forceinline__ void phase(float acc[2][8][4], FragPre& f0, FragPre& f1,
                                      uint32_t st_base, int kf,
                                      int m0, int n0, int tid,
                                      uint32_t offA0, uint32_t offA1,
                                      const uint32_t* offB) {
    constexpr int S1 = (P + 1) % STAGES;
    constexpr int S2 = (P + 2) % STAGES;
    constexpr int F0 = (P + 4) % STAGES;
    constexpr int F1 = (P + 5) % STAGES;
    const uint32_t sb0 = st_base + (uint32_t)(P  * STAGE_B);
    const uint32_t sb1 = st_base + (uint32_t)(S1 * STAGE_B);
    const uint32_t sb2 = st_base + (uint32_t)(S2 * STAGE_B);

    if (kf < 128) load_stage(st_base, F0, kf * 32, m0, n0, tid);

    chunk(acc, f0, f1, sb0, 0u,  sb0, 32u, offA0, offA1, offB);
    chunk(acc, f1, f0, sb0, 32u, sb1, 0u,  offA0, offA1, offB);

    if (kf + 1 < 128) load_stage(st_base, F1, (kf + 1) * 32, m0, n0, tid);

    chunk(acc, f0, f1, sb1, 0u,  sb1, 32u, offA0, offA1, offB);
    chunk(acc, f1, f0, sb1, 32u, sb2, 0u,  offA0, offA1, offB);

    if (!LAST) {
        asm volatile("cp.async.wait_group 1;" ::: "memory");
        __syncthreads();
    }
}

__global__ void __launch_bounds__(256, 2)
expander_gemm_kernel(float* __restrict__ out) {
    extern __shared__ char smem_raw[];
    const uint32_t st_base = smem_u32(smem_raw);

    const int tid  = threadIdx.x;
    const int lane = tid & 31;
    const int warp = tid >> 5;
    const int wm = warp & 3;        // 4 warps along M
    const int wn = warp >> 2;       // 2 warps along N
    const int mbase = wm * 32;
    const int nbase = wn * 64;

    // Rasterization: groups of 8 M-tiles x all 32 N-tiles for L2 reuse.
    const int TILES_N = DOUT / 128;               // 32
    const int per_g = 8 * TILES_N;                // 256
    int g   = blockIdx.x / per_g;
    int rem = blockIdx.x % per_g;
    int mt = g * 8 + (rem & 7);
    int nt = rem >> 3;
    const int m0 = mt * 128, n0 = nt * 128;

    // Per-thread ldmatrix addressing.
    const int a_row  = lane & 15;
    const int a_cadd = lane >> 4;
    const int b_row  = (lane & 7) + ((lane >> 3) & 1) * 8;
    const int b_cadd = lane >> 4;

    int rA0 = mbase + a_row, rA1 = mbase + 16 + a_row;
    const uint32_t offA0 = (uint32_t)rA0 * 64 + ((uint32_t)(a_cadd ^ ((rA0 >> 1) & 3)) << 4);
    const uint32_t offA1 = (uint32_t)rA1 * 64 + ((uint32_t)(a_cadd ^ ((rA1 >> 1) & 3)) << 4);
    uint32_t offB[4];
#pragma unroll
    for (int i4 = 0; i4 < 4; i4++) {
        int r = nbase + i4 * 16 + b_row;
        offB[i4] = 8192u + (uint32_t)r * 64 + ((uint32_t)(b_cadd ^ ((r >> 1) & 3)) << 4);
    }

    float acc[2][8][4];
#pragma unroll
    for (int a = 0; a < 2; a++)
#pragma unroll
        for (int b = 0; b < 8; b++)
#pragma unroll
            for (int c = 0; c < 4; c++) acc[a][b][c] = 0.f;

    // Prologue: fill stages 0..3 (k-steps 0..3).
#pragma unroll
    for (int s = 0; s < 4; s++)
        load_stage(st_base, s, s * 32, m0, n0, tid);

    asm volatile("cp.async.wait_group 1;" ::: "memory");
    __syncthreads();
    FragPre f0, f1;
    ld_pre(f0, st_base, 0u, offA0, offA1, offB);

    // 64 phases = 21 unrolled triples (slot period 3) + 1 tail phase.
    int kf = 4;
#pragma unroll 1
    for (int trip = 0; trip < 21; trip++) {
        phase<0>(acc, f0, f1, st_base, kf,     m0, n0, tid, offA0, offA1, offB);
        phase<2>(acc, f0, f1, st_base, kf + 2, m0, n0, tid, offA0, offA1, offB);
        phase<4>(acc, f0, f1, st_base, kf + 4, m0, n0, tid, offA0, offA1, offB);
        kf += 6;
    }
    phase<0, true>(acc, f0, f1, st_base, kf, m0, n0, tid, offA0, offA1, offB);

    // Epilogue: streaming stores (output is never re-read; keep it out of L2).
    const int gid = lane >> 2, tig = lane & 3;
#pragma unroll
    for (int im = 0; im < 2; im++) {
        int r0 = m0 + mbase + im * 16 + gid;
#pragma unroll
        for (int j8 = 0; j8 < 8; j8++) {
            int col = n0 + nbase + j8 * 8 + tig * 2;
            stg_cs_v2(out + (size_t)r0 * DOUT + col,
                      acc[im][j8][0], acc[im][j8][1]);
            stg_cs_v2(out + (size_t)(r0 + 8) * DOUT + col,
                      acc[im][j8][2], acc[im][j8][3]);
        }
    }
}

// ---------------------------------------------------------------------------
// Launch
// ---------------------------------------------------------------------------
extern "C" void kernel_launch(void* const* d_in, const int* in_sizes, int n_in,
                              void* d_out, int out_size) {
    const float* x    = (const float*)d_in[0];
    const float* w    = (const float*)d_in[1];
    const float* mask = (const float*)d_in[2];
    float* out = (float*)d_out;

    {
        int ntot2 = (NX4 + NW4) / 2;   // 2 float4 per thread
        convert_both_kernel<<<(ntot2 + 255) / 256, 256>>>(
            (const float4*)x, (const float4*)w, (const float4*)mask);
    }

    static bool attr_set = false;
    if (!attr_set) {
        cudaFuncSetAttribute(expander_gemm_kernel,
                             cudaFuncAttributeMaxDynamicSharedMemorySize, SMEM_B);
        attr_set = true;
    }
    int grid = (BATCH / 128) * (DOUT / 128);   // 2048
    expander_gemm_kernel<<<grid, 256, SMEM_B>>>(out);
}

// round 15
// speedup vs baseline: 1.0694x; 1.0309x over previous
#include <cuda_runtime.h>
#include <cuda_fp16.h>
#include <cstdint>
#include <cstddef>

#define BATCH 8192
#define DIN   4096
#define DOUT  4096

// fp16 scratch (module-load allocation; legal per harness rules)
__device__ __half g_Xh[(size_t)BATCH * DIN];   // 64 MB
__device__ __half g_Wh[(size_t)DOUT  * DIN];   // 32 MB

// ---------------------------------------------------------------------------
// Fused conversion kernel: x fp32->fp16 and w*mask fp32->fp16 in one launch.
// ---------------------------------------------------------------------------
static constexpr int NX4 = (BATCH * DIN) / 4;   // 8388608
static constexpr int NW4 = (DOUT  * DIN) / 4;   // 4194304

__device__ __forceinline__ uint2 cvt4(float4 v) {
    __half2 h0 = __floats2half2_rn(v.x, v.y);
    __half2 h1 = __floats2half2_rn(v.z, v.w);
    uint2 u;
    u.x = *reinterpret_cast<uint32_t*>(&h0);
    u.y = *reinterpret_cast<uint32_t*>(&h1);
    return u;
}

__global__ void __launch_bounds__(256)
convert_both_kernel(const float4* __restrict__ x,
                    const float4* __restrict__ w,
                    const float4* __restrict__ m) {
    int i0 = (blockIdx.x * blockDim.x + threadIdx.x) * 2;
    if (i0 + 1 < NX4) {
        float4 v0 = __ldg(x + i0);
        float4 v1 = __ldg(x + i0 + 1);
        reinterpret_cast<uint2*>(g_Xh)[i0]     = cvt4(v0);
        reinterpret_cast<uint2*>(g_Xh)[i0 + 1] = cvt4(v1);
    } else if (i0 < NX4 + NW4) {
        int j0 = i0 - NX4;
        if (i0 >= NX4 && j0 + 1 < NW4) {
            float4 w0 = __ldg(w + j0), m0v = __ldg(m + j0);
            float4 w1 = __ldg(w + j0 + 1), m1v = __ldg(m + j0 + 1);
            float4 a0 = make_float4(w0.x * m0v.x, w0.y * m0v.y, w0.z * m0v.z, w0.w * m0v.w);
            float4 a1 = make_float4(w1.x * m1v.x, w1.y * m1v.y, w1.z * m1v.z, w1.w * m1v.w);
            reinterpret_cast<uint2*>(g_Wh)[j0]     = cvt4(a0);
            reinterpret_cast<uint2*>(g_Wh)[j0 + 1] = cvt4(a1);
        }
    }
}

// ---------------------------------------------------------------------------
// GEMM: out[8192,4096] = Xh @ Wh^T, fp16 in / fp32 accum via mma.sync.m16n8k16
// CTA tile 128x128x32-per-stage, 8 warps (4M x 2N), warp tile 32x64.
// 6 stages, compile-time slot phases (period 3). LDSM addrs: sb + (off ^ x).
// Hot phases are compare-free (fill flag templated); fills issue AFTER the
// first chunk so the HMMA stream restarts immediately post-barrier.
// ---------------------------------------------------------------------------
static constexpr int STAGES  = 6;
static constexpr int STAGE_B = 16384;              // A 8KB + B 8KB
static constexpr int SMEM_B  = STAGES * STAGE_B;   // 96 KB

// 64B rows (32 halfs). 16B chunk c in 0..3, swizzle chunk XOR (row>>1)&3.
__device__ __forceinline__ uint32_t sw_off(int row, int c16) {
    return (uint32_t)(row * 64 + (((c16 ^ ((row >> 1) & 3)) << 4)));
}

__device__ __forceinline__ uint32_t smem_u32(const void* p) {
    uint32_t a;
    asm("{ .reg .u64 t; cvta.to.shared.u64 t, %1; cvt.u32.u64 %0, t; }"
        : "=r"(a) : "l"(p));
    return a;
}

__device__ __forceinline__ void ldsm_x4(uint32_t* r, uint32_t addr) {
    asm volatile("ldmatrix.sync.aligned.m8n8.x4.shared.b16 {%0,%1,%2,%3}, [%4];"
                 : "=r"(r[0]), "=r"(r[1]), "=r"(r[2]), "=r"(r[3]) : "r"(addr));
}

__device__ __forceinline__ void mma16816(float* c, const uint32_t* a,
                                         uint32_t b0, uint32_t b1) {
    asm volatile(
        "mma.sync.aligned.m16n8k16.row.col.f32.f16.f16.f32 "
        "{%0,%1,%2,%3}, {%4,%5,%6,%7}, {%8,%9}, {%0,%1,%2,%3};"
        : "+f"(c[0]), "+f"(c[1]), "+f"(c[2]), "+f"(c[3])
        : "r"(a[0]), "r"(a[1]), "r"(a[2]), "r"(a[3]), "r"(b0), "r"(b1));
}

__device__ __forceinline__ void stg_cs_v2(float* p, float a, float b) {
    float2 v = make_float2(a, b);
    asm volatile("st.global.cs.v2.f32 [%0], {%1, %2};"
                 :: "l"(p), "f"(v.x), "f"(v.y) : "memory");
}

__device__ __forceinline__ void load_stage(uint32_t st_base, int slot,
                                           int k0, int m0, int n0, int tid) {
    uint32_t base = st_base + (uint32_t)slot * STAGE_B;
#pragma unroll
    for (int i = 0; i < 4; i++) {
        int cid = i * 256 + tid;            // 0..1023 (A: <512, B: >=512)
        const __half* gp;
        uint32_t so;
        if (cid < 512) {                    // A: 128 rows x 4 chunks
            int row = cid >> 2, c = cid & 3;
            gp = g_Xh + (size_t)(m0 + row) * DIN + k0 + c * 8;
            so = base + sw_off(row, c);
        } else {                            // B: 128 rows x 4 chunks
            int row = (cid - 512) >> 2, c = cid & 3;
            gp = g_Wh + (size_t)(n0 + row) * DIN + k0 + c * 8;
            so = base + 8192 + sw_off(row, c);
        }
        asm volatile("cp.async.cg.shared.global [%0], [%1], 16;"
                     :: "r"(so), "l"(gp) : "memory");
    }
    asm volatile("cp.async.commit_group;" ::: "memory");
}

// Fragment set for one k16 chunk: A halves + first two B quads.
struct FragPre {
    uint32_t A0[4], A1[4], B0[4], B1[4];
};

// Addresses use sb + (off ^ x): sb multiple of 16384, off < 16384 (no carry),
// so XOR hoists and sb folds into the LDSM immediate.
__device__ __forceinline__ void ld_pre(FragPre& f, uint32_t sb, uint32_t x,
                                       uint32_t offA0, uint32_t offA1,
                                       const uint32_t* offB) {
    ldsm_x4(f.A0, sb + (offA0 ^ x));
    ldsm_x4(f.A1, sb + (offA1 ^ x));
    ldsm_x4(f.B0, sb + (offB[0] ^ x));
    ldsm_x4(f.B1, sb + (offB[1] ^ x));
}

// Process one k16 chunk (16 HMMAs), interleaving its own B2/B3 loads and the
// next chunk's pre-fragments.
__device__ __forceinline__ void chunk(float acc[2][8][4], FragPre& cur, FragPre& nxt,
                                      uint32_t sb, uint32_t x,
                                      uint32_t nsb, uint32_t nx,
                                      uint32_t offA0, uint32_t offA1,
                                      const uint32_t* offB) {
    uint32_t B2[4], B3[4];
    ldsm_x4(B2, sb + (offB[2] ^ x));
    mma16816(acc[0][0], cur.A0, cur.B0[0], cur.B0[2]);
    mma16816(acc[0][1], cur.A0, cur.B0[1], cur.B0[3]);
    ldsm_x4(B3, sb + (offB[3] ^ x));
    mma16816(acc[1][0], cur.A1, cur.B0[0], cur.B0[2]);
    mma16816(acc[1][1], cur.A1, cur.B0[1], cur.B0[3]);
    ldsm_x4(nxt.A0, nsb + (offA0 ^ nx));
    mma16816(acc[0][2], cur.A0, cur.B1[0], cur.B1[2]);
    mma16816(acc[0][3], cur.A0, cur.B1[1], cur.B1[3]);
    ldsm_x4(nxt.A1, nsb + (offA1 ^ nx));
    mma16816(acc[1][2], cur.A1, cur.B1[0], cur.B1[2]);
    mma16816(acc[1][3], cur.A1, cur.B1[1], cur.B1[3]);
    ldsm_x4(nxt.B0, nsb + (offB[0] ^ nx));
    mma16816(acc[0][4], cur.A0, B2[0], B2[2]);
    mma16816(acc[0][5], cur.A0, B2[1], B2[3]);
    ldsm_x4(nxt.B1, nsb + (offB[1] ^ nx));
    mma16816(acc[1][4], cur.A1, B2[0], B2[2]);
    mma16816(acc[1][5], cur.A1, B2[1], B2[3]);
    mma16816(acc[0][6], cur.A0, B3[0], B3[2]);
    mma16816(acc[0][7], cur.A0, B3[1], B3[3]);
    mma16816(acc[1][6], cur.A1, B3[0], B3[2]);
    mma16816(acc[1][7], cur.A1, B3[1], B3[3]);
}

// One phase = 2 k-steps (4 k16 chunks). GUARDED=false -> fills unconditional
// (hot path, no compares). Fills issue after chunks 0 and 2 so the post-
// barrier instruction stream starts with LDSMs.
template <int P, bool GUARDED, bool LAST = false>
__device__ __forceinline__ void phase(float acc[2][8][4], FragPre& f0, FragPre& f1,
                                      uint32_t st_base, int kf,
                                      int m0, int n0, int tid,
                                      uint32_t offA0, uint32_t offA1,
                                      const uint32_t* offB) {
    constexpr int S1 = (P + 1) % STAGES;
    constexpr int S2 = (P + 2) % STAGES;
    constexpr int F0 = (P + 4) % STAGES;
    constexpr int F1 = (P + 5) % STAGES;
    const uint32_t sb0 = st_base + (uint32_t)(P  * STAGE_B);
    const uint32_t sb1 = st_base + (uint32_t)(S1 * STAGE_B);
    const uint32_t sb2 = st_base + (uint32_t)(S2 * STAGE_B);

    chunk(acc, f0, f1, sb0, 0u,  sb0, 32u, offA0, offA1, offB);

    if (!GUARDED || kf < 128) load_stage(st_base, F0, kf * 32, m0, n0, tid);

    chunk(acc, f1, f0, sb0, 32u, sb1, 0u,  offA0, offA1, offB);
    chunk(acc, f0, f1, sb1, 0u,  sb1, 32u, offA0, offA1, offB);

    if (!GUARDED || kf + 1 < 128) load_stage(st_base, F1, (kf + 1) * 32, m0, n0, tid);

    chunk(acc, f1, f0, sb1, 32u, sb2, 0u,  offA0, offA1, offB);

    if (!LAST) {
        asm volatile("cp.async.wait_group 1;" ::: "memory");
        __syncthreads();
    }
}

__global__ void __launch_bounds__(256, 2)
expander_gemm_kernel(float* __restrict__ out) {
    extern __shared__ char smem_raw[];
    const uint32_t st_base = smem_u32(smem_raw);

    const int tid  = threadIdx.x;
    const int lane = tid & 31;
    const int warp = tid >> 5;
    const int wm = warp & 3;        // 4 warps along M
    const int wn = warp >> 2;       // 2 warps along N
    const int mbase = wm * 32;
    const int nbase = wn * 64;

    // Rasterization: groups of 8 M-tiles x all 32 N-tiles for L2 reuse.
    const int TILES_N = DOUT / 128;               // 32
    const int per_g = 8 * TILES_N;                // 256
    int g   = blockIdx.x / per_g;
    int rem = blockIdx.x % per_g;
    int mt = g * 8 + (rem & 7);
    int nt = rem >> 3;
    const int m0 = mt * 128, n0 = nt * 128;

    // Per-thread ldmatrix addressing.
    const int a_row  = lane & 15;
    const int a_cadd = lane >> 4;
    const int b_row  = (lane & 7) + ((lane >> 3) & 1) * 8;
    const int b_cadd = lane >> 4;

    int rA0 = mbase + a_row, rA1 = mbase + 16 + a_row;
    const uint32_t offA0 = (uint32_t)rA0 * 64 + ((uint32_t)(a_cadd ^ ((rA0 >> 1) & 3)) << 4);
    const uint32_t offA1 = (uint32_t)rA1 * 64 + ((uint32_t)(a_cadd ^ ((rA1 >> 1) & 3)) << 4);
    uint32_t offB[4];
#pragma unroll
    for (int i4 = 0; i4 < 4; i4++) {
        int r = nbase + i4 * 16 + b_row;
        offB[i4] = 8192u + (uint32_t)r * 64 + ((uint32_t)(b_cadd ^ ((r >> 1) & 3)) << 4);
    }

    float acc[2][8][4];
#pragma unroll
    for (int a = 0; a < 2; a++)
#pragma unroll
        for (int b = 0; b < 8; b++)
#pragma unroll
            for (int c = 0; c < 4; c++) acc[a][b][c] = 0.f;

    // Prologue: fill stages 0..3 (k-steps 0..3).
#pragma unroll
    for (int s = 0; s < 4; s++)
        load_stage(st_base, s, s * 32, m0, n0, tid);

    asm volatile("cp.async.wait_group 1;" ::: "memory");
    __syncthreads();
    FragPre f0, f1;
    ld_pre(f0, st_base, 0u, offA0, offA1, offB);

    // 64 phases: 20 hot trips (fills unconditional, kf <= 123), then a
    // guarded trip + guarded tail covering the fill boundary (kf 124..130).
    int kf = 4;
#pragma unroll 1
    for (int trip = 0; trip < 20; trip++) {
        phase<0, false>(acc, f0, f1, st_base, kf,     m0, n0, tid, offA0, offA1, offB);
        phase<2, false>(acc, f0, f1, st_base, kf + 2, m0, n0, tid, offA0, offA1, offB);
        phase<4, false>(acc, f0, f1, st_base, kf + 4, m0, n0, tid, offA0, offA1, offB);
        kf += 6;
    }
    // kf = 124
    phase<0, true>(acc, f0, f1, st_base, kf,     m0, n0, tid, offA0, offA1, offB);
    phase<2, true>(acc, f0, f1, st_base, kf + 2, m0, n0, tid, offA0, offA1, offB);
    phase<4, true>(acc, f0, f1, st_base, kf + 4, m0, n0, tid, offA0, offA1, offB);
    phase<0, true, true>(acc, f0, f1, st_base, kf + 6, m0, n0, tid, offA0, offA1, offB);

    // Epilogue: streaming stores (output is never re-read; keep it out of L2).
    const int gid = lane >> 2, tig = lane & 3;
#pragma unroll
    for (int im = 0; im < 2; im++) {
        int r0 = m0 + mbase + im * 16 + gid;
#pragma unroll
        for (int j8 = 0; j8 < 8; j8++) {
            int col = n0 + nbase + j8 * 8 + tig * 2;
            stg_cs_v2(out + (size_t)r0 * DOUT + col,
                      acc[im][j8][0], acc[im][j8][1]);
            stg_cs_v2(out + (size_t)(r0 + 8) * DOUT + col,
                      acc[im][j8][2], acc[im][j8][3]);
        }
    }
}

// ---------------------------------------------------------------------------
// Launch
// ---------------------------------------------------------------------------
extern "C" void kernel_launch(void* const* d_in, const int* in_sizes, int n_in,
                              void* d_out, int out_size) {
    const float* x    = (const float*)d_in[0];
    const float* w    = (const float*)d_in[1];
    const float* mask = (const float*)d_in[2];
    float* out = (float*)d_out;

    {
        int ntot2 = (NX4 + NW4) / 2;   // 2 float4 per thread
        convert_both_kernel<<<(ntot2 + 255) / 256, 256>>>(
            (const float4*)x, (const float4*)w, (const float4*)mask);
    }

    static bool attr_set = false;
    if (!attr_set) {
        cudaFuncSetAttribute(expander_gemm_kernel,
                             cudaFuncAttributeMaxDynamicSharedMemorySize, SMEM_B);
        attr_set = true;
    }
    int grid = (BATCH / 128) * (DOUT / 128);   // 2048
    expander_gemm_kernel<<<grid, 256, SMEM_B>>>(out);
}